// round 7
// baseline (speedup 1.0000x reference)
#include <cuda_runtime.h>
#include <math.h>

#define BQ    8
#define SEQ   512
#define NVAR  1024
#define TFEAT 7
#define LTOK  1031           // NVAR + TFEAT
#define MTOT  8248           // BQ * LTOK
#define DMOD  128
#define DST   16
#define PREDN 96
#define NCH   32
#define CLEN  33             // ceil(LTOK/NCH)

// ---------------- scratch (device globals; no allocation allowed) ----------------
__device__ float g_tok[MTOT * SEQ];
__device__ float g_h  [MTOT * DMOD];
__device__ float g_ln1[MTOT * DMOD];
__device__ float g_ffn[MTOT * DMOD];
__device__ float g_xz [MTOT * 512];
__device__ float g_xc [2 * MTOT * DMOD];
__device__ float g_dbc[2 * MTOT * 160];
__device__ float g_y  [MTOT * 256];
__device__ float g_po [MTOT * PREDN];
__device__ float g_wxp[4 * 160 * DMOD];
__device__ float g_wop[2 * DMOD * 256];
__device__ float g_sA [BQ * 2 * NCH * DMOD * DST];
__device__ float g_sH [BQ * 2 * NCH * DMOD * DST];
__device__ float g_sS [BQ * 2 * NCH * DMOD * DST];

// ---------------- token transpose + mask ----------------
__global__ void tok_prep(const float* __restrict__ x_enc, float* __restrict__ tok)
{
    __shared__ float tile[32][33];
    int b = blockIdx.z;
    int s0 = blockIdx.x * 32, v0 = blockIdx.y * 32;
    #pragma unroll
    for (int i = 0; i < 4; i++) {
        int s = s0 + threadIdx.y + i * 8;
        float x = x_enc[((size_t)(b * SEQ + s)) * NVAR + v0 + threadIdx.x];
        tile[threadIdx.y + i * 8][threadIdx.x] = (x == -9999.0f) ? -1.0f : x;
    }
    __syncthreads();
    #pragma unroll
    for (int i = 0; i < 4; i++) {
        int v = v0 + threadIdx.y + i * 8;
        tok[((size_t)(b * LTOK + v)) * SEQ + s0 + threadIdx.x] = tile[threadIdx.x][threadIdx.y + i * 8];
    }
}

__global__ void mark_prep(const float* __restrict__ x_mark, float* __restrict__ tok)
{
    int idx = blockIdx.x * 256 + threadIdx.x;
    if (idx >= BQ * TFEAT * SEQ) return;
    int s = idx & (SEQ - 1);
    int r = idx >> 9;
    int f = r % TFEAT;
    int b = r / TFEAT;
    tok[((size_t)(b * LTOK + NVAR + f)) * SEQ + s] = x_mark[((size_t)(b * SEQ + s)) * TFEAT + f];
}

// ---------------- combined x_proj/dt_proj weight prep ----------------
__global__ void prep_wd(const float* __restrict__ xpw, const float* __restrict__ dpw,
                        float* __restrict__ out)
{
    int ld = blockIdx.y;
    int idx = blockIdx.x * 256 + threadIdx.x;
    if (idx >= 160 * DMOD) return;
    int i = idx / DMOD, j = idx - i * DMOD;
    const float* xp = xpw + ld * 40 * DMOD;
    float v;
    if (i < DMOD) {
        const float* dp = dpw + (ld * DMOD + i) * 8;
        v = 0.f;
        #pragma unroll
        for (int r = 0; r < 8; r++) v += dp[r] * xp[r * DMOD + j];
    } else {
        v = xp[(8 + (i - DMOD)) * DMOD + j];
    }
    out[ld * 160 * DMOD + idx] = v;
}

// ---------------- out_proj weight concat ----------------
__global__ void prep_wop(const float* __restrict__ opw, float* __restrict__ out)
{
    int idx = blockIdx.x * 256 + threadIdx.x;
    if (idx >= 2 * DMOD * 256) return;
    int l = idx / (DMOD * 256);
    int r = idx - l * DMOD * 256;
    int n = r >> 8;
    int k = r & 255;
    int dir = k >> 7;
    int kk = k & 127;
    out[idx] = opw[(((size_t)(l * 2 + dir) * DMOD) + n) * DMOD + kk];
}

// ---------------- fp32 GEMM: C[M,N] = A[M,K] @ W[N,K]^T (+epilogue) --------------
// 128 threads, BM=128, BN=64, BK=16. Warp grid 2x2 (64x32 warp tile).
// Thread tile 8x8 as row groups {lm*4, lm*4+32} x col groups {ln*4, ln*4+16}.
// All fragment LDS.128 span exactly 128B across the warp -> conflict-free.
template<int EPI>
__global__ __launch_bounds__(128) void gemm_k(
    const float* __restrict__ A, const float* __restrict__ W,
    const float* __restrict__ bias, const float* __restrict__ resid,
    float* __restrict__ C, int M, int N, int K,
    size_t sA, size_t sW, size_t sB, size_t sC)
{
    if (gridDim.z > 1) {
        A += (size_t)blockIdx.z * sA;
        W += (size_t)blockIdx.z * sW;
        C += (size_t)blockIdx.z * sC;
        if (bias)  bias  += (size_t)blockIdx.z * sB;
        if (resid) resid += (size_t)blockIdx.z * sC;
    }
    __shared__ float As[2][16][128];
    __shared__ float Bs[2][16][64];
    int bm = blockIdx.y * 128;
    int bn = blockIdx.x * 64;
    int tid = threadIdx.x;

    int wid = tid >> 5, lane = tid & 31;
    int warp_m = wid >> 1, warp_n = wid & 1;
    int lm = lane >> 2, ln = lane & 3;
    int rA = warp_m * 64 + lm * 4;      // rows rA..rA+3 and rA+32..rA+35
    int rB = warp_n * 32 + ln * 4;      // cols rB..rB+3 and rB+16..rB+19

    // A loader: thread -> row tid, full 16-float slice
    int ar = tid;
    bool aact = (bm + ar < M);
    const float* Ap = A + (size_t)(bm + ar) * K;

    // B loader: thread -> row tid>>1, 8-float half (tid&1)
    int br = tid >> 1;
    int bc = (tid & 1) * 8;
    bool wact = (bn + br < N);
    const float* Wp = W + (size_t)(bn + br) * K + bc;

    float acc[8][8] = {};
    float4 ra[4], rb[2];
    #pragma unroll
    for (int q = 0; q < 4; q++) ra[q] = make_float4(0,0,0,0);
    rb[0] = make_float4(0,0,0,0); rb[1] = make_float4(0,0,0,0);

    if (aact) {
        #pragma unroll
        for (int q = 0; q < 4; q++) ra[q] = *(const float4*)(Ap + q * 4);
    }
    if (wact) { rb[0] = *(const float4*)(Wp); rb[1] = *(const float4*)(Wp + 4); }
    {
        #pragma unroll
        for (int q = 0; q < 4; q++) {
            As[0][q*4+0][ar] = ra[q].x; As[0][q*4+1][ar] = ra[q].y;
            As[0][q*4+2][ar] = ra[q].z; As[0][q*4+3][ar] = ra[q].w;
        }
        Bs[0][bc+0][br] = rb[0].x; Bs[0][bc+1][br] = rb[0].y;
        Bs[0][bc+2][br] = rb[0].z; Bs[0][bc+3][br] = rb[0].w;
        Bs[0][bc+4][br] = rb[1].x; Bs[0][bc+5][br] = rb[1].y;
        Bs[0][bc+6][br] = rb[1].z; Bs[0][bc+7][br] = rb[1].w;
    }
    __syncthreads();

    int NT = K >> 4;
    for (int t = 0; t < NT; t++) {
        int buf = t & 1;
        if (t + 1 < NT) {
            int k0 = (t + 1) << 4;
            if (aact) {
                #pragma unroll
                for (int q = 0; q < 4; q++) ra[q] = *(const float4*)(Ap + k0 + q * 4);
            }
            if (wact) { rb[0] = *(const float4*)(Wp + k0); rb[1] = *(const float4*)(Wp + k0 + 4); }
        }
        #pragma unroll
        for (int k = 0; k < 16; k++) {
            float4 a0 = *(const float4*)&As[buf][k][rA];
            float4 a1 = *(const float4*)&As[buf][k][rA + 32];
            float4 b0 = *(const float4*)&Bs[buf][k][rB];
            float4 b1 = *(const float4*)&Bs[buf][k][rB + 16];
            float av[8] = {a0.x, a0.y, a0.z, a0.w, a1.x, a1.y, a1.z, a1.w};
            float bv[8] = {b0.x, b0.y, b0.z, b0.w, b1.x, b1.y, b1.z, b1.w};
            #pragma unroll
            for (int i = 0; i < 8; i++)
                #pragma unroll
                for (int j = 0; j < 8; j++)
                    acc[i][j] = fmaf(av[i], bv[j], acc[i][j]);
        }
        if (t + 1 < NT) {
            int nb = buf ^ 1;
            #pragma unroll
            for (int q = 0; q < 4; q++) {
                As[nb][q*4+0][ar] = ra[q].x; As[nb][q*4+1][ar] = ra[q].y;
                As[nb][q*4+2][ar] = ra[q].z; As[nb][q*4+3][ar] = ra[q].w;
            }
            Bs[nb][bc+0][br] = rb[0].x; Bs[nb][bc+1][br] = rb[0].y;
            Bs[nb][bc+2][br] = rb[0].z; Bs[nb][bc+3][br] = rb[0].w;
            Bs[nb][bc+4][br] = rb[1].x; Bs[nb][bc+5][br] = rb[1].y;
            Bs[nb][bc+6][br] = rb[1].z; Bs[nb][bc+7][br] = rb[1].w;
            __syncthreads();
        }
    }

    #pragma unroll
    for (int i = 0; i < 8; i++) {
        int m = bm + rA + ((i < 4) ? i : (28 + i));   // i>=4 -> +32+(i-4)
        if (m >= M) continue;
        #pragma unroll
        for (int j = 0; j < 8; j++) {
            int n = bn + rB + ((j < 4) ? j : (12 + j)); // j>=4 -> +16+(j-4)
            if (n >= N) continue;
            float v = acc[i][j];
            if (EPI == 0) {
                if (bias) v += bias[n];
            } else if (EPI == 1) {
                v = fmaxf(v + bias[n], 0.f);
            } else if (EPI == 2) {
                if (bias) v += bias[n];
                v += resid[(size_t)m * N + n];
            } else if (EPI == 3) {
                if (n < DMOD) {
                    v += bias[n];
                    v = (v > 20.f) ? v : log1pf(__expf(v));
                }
            }
            C[(size_t)m * N + n] = v;
        }
    }
}

// ---------------- depthwise causal conv (DCONV=2) + silu ----------------
__global__ void conv_silu(const float* __restrict__ xz, const float* __restrict__ cw,
                          const float* __restrict__ cb, float* __restrict__ xc, int l)
{
    int idx = blockIdx.x * 256 + threadIdx.x;
    if (idx >= 2 * MTOT * DMOD) return;
    int dir = idx / (MTOT * DMOD);
    int rem = idx - dir * (MTOT * DMOD);
    int row = rem >> 7;
    int d = rem & (DMOD - 1);
    int b = row / LTOK;
    int tau = row - b * LTOK;
    int t = dir ? (LTOK - 1 - tau) : tau;
    int ld = l * 2 + dir;
    float c0 = cw[(ld * DMOD + d) * 2 + 0];
    float c1 = cw[(ld * DMOD + d) * 2 + 1];
    float x1 = xz[((size_t)(b * LTOK + t)) * 512 + dir * 256 + d];
    float acc = x1 * c1 + cb[ld * DMOD + d];
    if (tau > 0) {
        int tp = dir ? (t + 1) : (t - 1);
        acc += xz[((size_t)(b * LTOK + tp)) * 512 + dir * 256 + d] * c0;
    }
    acc = acc / (1.f + __expf(-acc));
    xc[(size_t)dir * MTOT * DMOD + rem] = acc;
}

// ---------------- chunked selective scan (thread = d, 16 states in regs) ---------
__global__ __launch_bounds__(128) void scan_p1(
    const float* __restrict__ dbc, const float* __restrict__ xc,
    const float* __restrict__ A_log, float* __restrict__ sA, float* __restrict__ sH, int l)
{
    int d  = threadIdx.x;
    int c  = blockIdx.x;
    int b  = blockIdx.y;
    int dir = blockIdx.z;
    int ld = l * 2 + dir;

    float a[DST];
    {
        const float* Ab = A_log + ((size_t)(ld * DMOD + d)) * DST;
        #pragma unroll
        for (int q = 0; q < 4; q++) {
            float4 v = *(const float4*)(Ab + q * 4);
            a[q*4+0] = -__expf(v.x); a[q*4+1] = -__expf(v.y);
            a[q*4+2] = -__expf(v.z); a[q*4+3] = -__expf(v.w);
        }
    }
    const float* dbcp = dbc + (size_t)dir * MTOT * 160 + (size_t)b * LTOK * 160;
    const float* xcp  = xc  + (size_t)dir * MTOT * DMOD + (size_t)b * LTOK * DMOD;

    int t0 = c * CLEN;
    int t1 = t0 + CLEN; if (t1 > LTOK) t1 = LTOK;

    float Aacc[DST], h[DST];
    #pragma unroll
    for (int n = 0; n < DST; n++) { Aacc[n] = 1.f; h[n] = 0.f; }

    for (int t = t0; t < t1; t++) {
        const float* row = dbcp + (size_t)t * 160;
        float delta = row[d];
        float xcv   = xcp[(size_t)t * DMOD + d];
        float dbx   = delta * xcv;
        float Bv[DST];
        #pragma unroll
        for (int q = 0; q < 4; q++) {
            float4 v = *(const float4*)(row + 128 + q * 4);
            Bv[q*4+0] = v.x; Bv[q*4+1] = v.y; Bv[q*4+2] = v.z; Bv[q*4+3] = v.w;
        }
        #pragma unroll
        for (int n = 0; n < DST; n++) {
            float dA = __expf(delta * a[n]);
            Aacc[n] *= dA;
            h[n] = fmaf(dA, h[n], dbx * Bv[n]);
        }
    }
    size_t base = (((size_t)(b * 2 + dir) * NCH + c) * DMOD + d) * DST;
    #pragma unroll
    for (int q = 0; q < 4; q++) {
        *(float4*)(sA + base + q * 4) = make_float4(Aacc[q*4], Aacc[q*4+1], Aacc[q*4+2], Aacc[q*4+3]);
        *(float4*)(sH + base + q * 4) = make_float4(h[q*4], h[q*4+1], h[q*4+2], h[q*4+3]);
    }
}

__global__ void scan_comb(const float* __restrict__ sA, const float* __restrict__ sH,
                          float* __restrict__ sS)
{
    int idx = blockIdx.x * 256 + threadIdx.x;
    if (idx >= BQ * 2 * DMOD * DST) return;
    int dn = idx & (DMOD * DST - 1);
    int bd = idx >> 11;
    size_t base = (size_t)bd * NCH * DMOD * DST + dn;
    float h = 0.f;
    #pragma unroll
    for (int c = 0; c < NCH; c++) {
        size_t p = base + (size_t)c * DMOD * DST;
        sS[p] = h;
        h = fmaf(sA[p], h, sH[p]);
    }
}

__global__ __launch_bounds__(128) void scan_p2(
    const float* __restrict__ dbc, const float* __restrict__ xc,
    const float* __restrict__ xz, const float* __restrict__ A_log,
    const float* __restrict__ Dpar, const float* __restrict__ sS,
    float* __restrict__ y, int l)
{
    int d  = threadIdx.x;
    int c  = blockIdx.x;
    int b  = blockIdx.y;
    int dir = blockIdx.z;
    int ld = l * 2 + dir;

    float a[DST];
    {
        const float* Ab = A_log + ((size_t)(ld * DMOD + d)) * DST;
        #pragma unroll
        for (int q = 0; q < 4; q++) {
            float4 v = *(const float4*)(Ab + q * 4);
            a[q*4+0] = -__expf(v.x); a[q*4+1] = -__expf(v.y);
            a[q*4+2] = -__expf(v.z); a[q*4+3] = -__expf(v.w);
        }
    }
    float Dp = Dpar[ld * DMOD + d];
    const float* dbcp = dbc + (size_t)dir * MTOT * 160 + (size_t)b * LTOK * 160;
    const float* xcp  = xc  + (size_t)dir * MTOT * DMOD + (size_t)b * LTOK * DMOD;
    const float* zp   = xz  + (size_t)b * LTOK * 512 + 128 + dir * 256;
    float*       yp   = y   + (size_t)b * LTOK * 256 + dir * 128;

    int t0 = c * CLEN;
    int t1 = t0 + CLEN; if (t1 > LTOK) t1 = LTOK;

    float h[DST];
    {
        size_t base = (((size_t)(b * 2 + dir) * NCH + c) * DMOD + d) * DST;
        #pragma unroll
        for (int q = 0; q < 4; q++) {
            float4 v = *(const float4*)(sS + base + q * 4);
            h[q*4+0] = v.x; h[q*4+1] = v.y; h[q*4+2] = v.z; h[q*4+3] = v.w;
        }
    }

    for (int tau = t0; tau < t1; tau++) {
        const float* row = dbcp + (size_t)tau * 160;
        float delta = row[d];
        float xcv   = xcp[(size_t)tau * DMOD + d];
        float dbx   = delta * xcv;
        float Bv[DST], Cv[DST];
        #pragma unroll
        for (int q = 0; q < 4; q++) {
            float4 v = *(const float4*)(row + 128 + q * 4);
            Bv[q*4+0] = v.x; Bv[q*4+1] = v.y; Bv[q*4+2] = v.z; Bv[q*4+3] = v.w;
            float4 u = *(const float4*)(row + 144 + q * 4);
            Cv[q*4+0] = u.x; Cv[q*4+1] = u.y; Cv[q*4+2] = u.z; Cv[q*4+3] = u.w;
        }
        float acc = 0.f;
        #pragma unroll
        for (int n = 0; n < DST; n++) {
            float dA = __expf(delta * a[n]);
            h[n] = fmaf(dA, h[n], dbx * Bv[n]);
            acc = fmaf(h[n], Cv[n], acc);
        }
        int t = dir ? (LTOK - 1 - tau) : tau;
        float zv = zp[(size_t)t * 512 + d];
        float sz = zv / (1.f + __expf(-zv));
        yp[(size_t)t * 256 + d] = (acc + Dp * xcv) * sz;
    }
}

// ---------------- layernorm: warp per row, 8 rows/block ----------------
__global__ __launch_bounds__(256) void ln_k(const float* __restrict__ in, float* __restrict__ out,
                                            const float* __restrict__ w, const float* __restrict__ b)
{
    int warp = threadIdx.x >> 5, lane = threadIdx.x & 31;
    int row = blockIdx.x * 8 + warp;
    const float4 v4 = *(const float4*)(in + (size_t)row * DMOD + lane * 4);
    float s = v4.x + v4.y + v4.z + v4.w;
    #pragma unroll
    for (int o = 16; o; o >>= 1) s += __shfl_xor_sync(0xffffffffu, s, o);
    float mu = s * (1.f / 128.f);
    float dx = v4.x - mu, dy = v4.y - mu, dz = v4.z - mu, dw = v4.w - mu;
    float q = dx*dx + dy*dy + dz*dz + dw*dw;
    #pragma unroll
    for (int o = 16; o; o >>= 1) q += __shfl_xor_sync(0xffffffffu, q, o);
    float rs = rsqrtf(q * (1.f / 128.f) + 1e-5f);
    float4 w4 = *(const float4*)(w + lane * 4);
    float4 b4 = *(const float4*)(b + lane * 4);
    float4 o4;
    o4.x = dx * rs * w4.x + b4.x;
    o4.y = dy * rs * w4.y + b4.y;
    o4.z = dz * rs * w4.z + b4.z;
    o4.w = dw * rs * w4.w + b4.w;
    *(float4*)(out + (size_t)row * DMOD + lane * 4) = o4;
}

// ---------------- final transposed write ----------------
__global__ void write_out(const float* __restrict__ P, float* __restrict__ out)
{
    int idx = blockIdx.x * 256 + threadIdx.x;
    if (idx >= BQ * PREDN * NVAR) return;
    int v = idx & (NVAR - 1);
    int p = (idx >> 10) % PREDN;
    int b = idx / (PREDN * NVAR);
    out[idx] = P[((size_t)(b * LTOK + v)) * PREDN + p];
}

// ---------------- launcher ----------------
extern "C" void kernel_launch(void* const* d_in, const int* in_sizes, int n_in,
                              void* d_out, int out_size)
{
    const float* x_enc     = (const float*)d_in[0];
    const float* x_mark    = (const float*)d_in[1];
    const float* emb_w     = (const float*)d_in[4];
    const float* emb_b     = (const float*)d_in[5];
    const float* in_proj_w = (const float*)d_in[6];
    const float* conv_w    = (const float*)d_in[7];
    const float* conv_b    = (const float*)d_in[8];
    const float* x_proj_w  = (const float*)d_in[9];
    const float* dt_proj_w = (const float*)d_in[10];
    const float* dt_proj_b = (const float*)d_in[11];
    const float* A_log     = (const float*)d_in[12];
    const float* D_param   = (const float*)d_in[13];
    const float* out_projw = (const float*)d_in[14];
    const float* norm1_w   = (const float*)d_in[15];
    const float* norm1_b   = (const float*)d_in[16];
    const float* norm2_w   = (const float*)d_in[17];
    const float* norm2_b   = (const float*)d_in[18];
    const float* ffn_w1    = (const float*)d_in[19];
    const float* ffn_b1    = (const float*)d_in[20];
    const float* ffn_w2    = (const float*)d_in[21];
    const float* ffn_b2    = (const float*)d_in[22];
    const float* fnorm_w   = (const float*)d_in[23];
    const float* fnorm_b   = (const float*)d_in[24];
    const float* proj_w    = (const float*)d_in[25];
    const float* proj_b    = (const float*)d_in[26];

    float *ptok, *ph, *pln1, *pffn, *pxz, *pxc, *pdbc, *py, *ppo, *pwxp, *pwop;
    float *psA, *psH, *psS;
    cudaGetSymbolAddress((void**)&ptok, g_tok);
    cudaGetSymbolAddress((void**)&ph,   g_h);
    cudaGetSymbolAddress((void**)&pln1, g_ln1);
    cudaGetSymbolAddress((void**)&pffn, g_ffn);
    cudaGetSymbolAddress((void**)&pxz,  g_xz);
    cudaGetSymbolAddress((void**)&pxc,  g_xc);
    cudaGetSymbolAddress((void**)&pdbc, g_dbc);
    cudaGetSymbolAddress((void**)&py,   g_y);
    cudaGetSymbolAddress((void**)&ppo,  g_po);
    cudaGetSymbolAddress((void**)&pwxp, g_wxp);
    cudaGetSymbolAddress((void**)&pwop, g_wop);
    cudaGetSymbolAddress((void**)&psA,  g_sA);
    cudaGetSymbolAddress((void**)&psH,  g_sH);
    cudaGetSymbolAddress((void**)&psS,  g_sS);

    const int MT = (MTOT + 127) / 128;   // 65

    // launch index 3 = in_proj GEMM of layer 0 (the one ncu captures)
    tok_prep<<<dim3(SEQ / 32, NVAR / 32, BQ), dim3(32, 8)>>>(x_enc, ptok);          // 0
    mark_prep<<<(BQ * TFEAT * SEQ + 255) / 256, 256>>>(x_mark, ptok);               // 1
    gemm_k<0><<<dim3(2, MT), 128>>>(ptok, emb_w, emb_b, nullptr, ph,                // 2
                                    MTOT, DMOD, SEQ, 0, 0, 0, 0);
    gemm_k<0><<<dim3(8, MT), 128>>>(ph, in_proj_w, nullptr, nullptr, pxz,           // 3 (profiled)
                                    MTOT, 512, DMOD, 0, 0, 0, 0);
    prep_wd<<<dim3(80, 4), 256>>>(x_proj_w, dt_proj_w, pwxp);
    prep_wop<<<(2 * DMOD * 256 + 255) / 256, 256>>>(out_projw, pwop);

    for (int l = 0; l < 2; l++) {
        if (l > 0)
            gemm_k<0><<<dim3(8, MT), 128>>>(ph, in_proj_w + (size_t)l * 2 * 256 * DMOD,
                                            nullptr, nullptr, pxz, MTOT, 512, DMOD, 0, 0, 0, 0);
        conv_silu<<<(2 * MTOT * DMOD + 255) / 256, 256>>>(pxz, conv_w, conv_b, pxc, l);
        gemm_k<3><<<dim3(3, MT, 2), 128>>>(pxc, pwxp + (size_t)l * 2 * 160 * DMOD,
                                           dt_proj_b + (size_t)l * 2 * DMOD, nullptr, pdbc,
                                           MTOT, 160, DMOD,
                                           (size_t)MTOT * DMOD, (size_t)160 * DMOD,
                                           (size_t)DMOD, (size_t)MTOT * 160);
        scan_p1<<<dim3(NCH, BQ, 2), 128>>>(pdbc, pxc, A_log, psA, psH, l);
        scan_comb<<<(BQ * 2 * DMOD * DST + 255) / 256, 256>>>(psA, psH, psS);
        scan_p2<<<dim3(NCH, BQ, 2), 128>>>(pdbc, pxc, pxz, A_log, D_param, psS, py, l);
        gemm_k<2><<<dim3(2, MT), 128>>>(py, pwop + (size_t)l * DMOD * 256,
                                        nullptr, ph, ph, MTOT, DMOD, 256, 0, 0, 0, 0);
        ln_k<<<MTOT / 8, 256>>>(ph, pln1, norm1_w + l * DMOD, norm1_b + l * DMOD);
        gemm_k<1><<<dim3(2, MT), 128>>>(pln1, ffn_w1 + (size_t)l * DMOD * DMOD,
                                        ffn_b1 + l * DMOD, nullptr, pffn,
                                        MTOT, DMOD, DMOD, 0, 0, 0, 0);
        gemm_k<2><<<dim3(2, MT), 128>>>(pffn, ffn_w2 + (size_t)l * DMOD * DMOD,
                                        ffn_b2 + l * DMOD, pln1, ph, MTOT, DMOD, DMOD, 0, 0, 0, 0);
        ln_k<<<MTOT / 8, 256>>>(ph, ph, norm2_w + l * DMOD, norm2_b + l * DMOD);
    }

    ln_k<<<MTOT / 8, 256>>>(ph, pln1, fnorm_w, fnorm_b);
    gemm_k<0><<<dim3(2, MT), 128>>>(pln1, proj_w, proj_b, nullptr, ppo,
                                    MTOT, PREDN, DMOD, 0, 0, 0, 0);
    write_out<<<(BQ * PREDN * NVAR + 255) / 256, 256>>>(ppo, (float*)d_out);
}

// round 8
// speedup vs baseline: 1.3243x; 1.3243x over previous
#include <cuda_runtime.h>
#include <math.h>
#include <stdint.h>

#define BQ    8
#define SEQ   512
#define NVAR  1024
#define TFEAT 7
#define LTOK  1031           // NVAR + TFEAT
#define MTOT  8248           // BQ * LTOK
#define DMOD  128
#define DST   16
#define PREDN 96
#define NCH   32
#define CLEN  33             // ceil(LTOK/NCH)

#define ASTRIDE 20           // smem row stride (floats) for conflict-free ldmatrix
#define ASMEM (128 * ASTRIDE)
#define BSMEM (64 * ASTRIDE)

// ---------------- scratch (device globals; no allocation allowed) ----------------
__device__ float g_tok[MTOT * SEQ];
__device__ float g_h  [MTOT * DMOD];
__device__ float g_ln1[MTOT * DMOD];
__device__ float g_ffn[MTOT * DMOD];
__device__ float g_xz [MTOT * 512];
__device__ float g_xc [2 * MTOT * DMOD];
__device__ float g_dbc[2 * MTOT * 160];
__device__ float g_y  [MTOT * 256];
__device__ float g_po [MTOT * PREDN];
__device__ float g_wxp[4 * 160 * DMOD];
__device__ float g_wop[2 * DMOD * 256];
__device__ float g_sA [BQ * 2 * NCH * DMOD * DST];
__device__ float g_sH [BQ * 2 * NCH * DMOD * DST];
__device__ float g_sS [BQ * 2 * NCH * DMOD * DST];

// ---------------- tensor-core helpers ----------------
__device__ __forceinline__ uint32_t f2tf32(float v)
{
    uint32_t r;
    asm("cvt.rna.tf32.f32 %0, %1;" : "=r"(r) : "f"(v));
    return r;
}

__device__ __forceinline__ void ldsm4(uint32_t* r, uint32_t addr)
{
    asm volatile("ldmatrix.sync.aligned.m8n8.x4.shared.b16 {%0,%1,%2,%3}, [%4];"
        : "=r"(r[0]), "=r"(r[1]), "=r"(r[2]), "=r"(r[3]) : "r"(addr));
}

__device__ __forceinline__ void mma_tf32(float* d, const uint32_t* a, uint32_t b0, uint32_t b1)
{
    asm volatile("mma.sync.aligned.m16n8k8.row.col.f32.tf32.tf32.f32 "
        "{%0,%1,%2,%3}, {%4,%5,%6,%7}, {%8,%9}, {%0,%1,%2,%3};"
        : "+f"(d[0]), "+f"(d[1]), "+f"(d[2]), "+f"(d[3])
        : "r"(a[0]), "r"(a[1]), "r"(a[2]), "r"(a[3]), "r"(b0), "r"(b1));
}

// ---------------- token transpose + mask ----------------
__global__ void tok_prep(const float* __restrict__ x_enc, float* __restrict__ tok)
{
    __shared__ float tile[32][33];
    int b = blockIdx.z;
    int s0 = blockIdx.x * 32, v0 = blockIdx.y * 32;
    #pragma unroll
    for (int i = 0; i < 4; i++) {
        int s = s0 + threadIdx.y + i * 8;
        float x = x_enc[((size_t)(b * SEQ + s)) * NVAR + v0 + threadIdx.x];
        tile[threadIdx.y + i * 8][threadIdx.x] = (x == -9999.0f) ? -1.0f : x;
    }
    __syncthreads();
    #pragma unroll
    for (int i = 0; i < 4; i++) {
        int v = v0 + threadIdx.y + i * 8;
        tok[((size_t)(b * LTOK + v)) * SEQ + s0 + threadIdx.x] = tile[threadIdx.x][threadIdx.y + i * 8];
    }
}

__global__ void mark_prep(const float* __restrict__ x_mark, float* __restrict__ tok)
{
    int idx = blockIdx.x * 256 + threadIdx.x;
    if (idx >= BQ * TFEAT * SEQ) return;
    int s = idx & (SEQ - 1);
    int r = idx >> 9;
    int f = r % TFEAT;
    int b = r / TFEAT;
    tok[((size_t)(b * LTOK + NVAR + f)) * SEQ + s] = x_mark[((size_t)(b * SEQ + s)) * TFEAT + f];
}

// ---------------- combined x_proj/dt_proj weight prep ----------------
__global__ void prep_wd(const float* __restrict__ xpw, const float* __restrict__ dpw,
                        float* __restrict__ out)
{
    int ld = blockIdx.y;
    int idx = blockIdx.x * 256 + threadIdx.x;
    if (idx >= 160 * DMOD) return;
    int i = idx / DMOD, j = idx - i * DMOD;
    const float* xp = xpw + ld * 40 * DMOD;
    float v;
    if (i < DMOD) {
        const float* dp = dpw + (ld * DMOD + i) * 8;
        v = 0.f;
        #pragma unroll
        for (int r = 0; r < 8; r++) v += dp[r] * xp[r * DMOD + j];
    } else {
        v = xp[(8 + (i - DMOD)) * DMOD + j];
    }
    out[ld * 160 * DMOD + idx] = v;
}

// ---------------- out_proj weight concat ----------------
__global__ void prep_wop(const float* __restrict__ opw, float* __restrict__ out)
{
    int idx = blockIdx.x * 256 + threadIdx.x;
    if (idx >= 2 * DMOD * 256) return;
    int l = idx / (DMOD * 256);
    int r = idx - l * DMOD * 256;
    int n = r >> 8;
    int k = r & 255;
    int dir = k >> 7;
    int kk = k & 127;
    out[idx] = opw[(((size_t)(l * 2 + dir) * DMOD) + n) * DMOD + kk];
}

// ---------------- TF32 tensor-core GEMM: C[M,N] = A[M,K] @ W[N,K]^T (+epilogue) --
// 256 threads / 8 warps. BM=128, BN=64, BK=16. Warp grid 4x2 -> 32x32 warp tile
// = 2 m16-tiles x 4 n8-tiles. 3-term tf32 split per product for ~fp32 accuracy.
// Smem: As[m][k] stride 20, Bs[n][k] stride 20 (both natural row-major copies).
template<int EPI>
__global__ __launch_bounds__(256) void gemm_tc(
    const float* __restrict__ A, const float* __restrict__ W,
    const float* __restrict__ bias, const float* __restrict__ resid,
    float* __restrict__ C, int M, int N, int K,
    size_t sA, size_t sW, size_t sB, size_t sC)
{
    if (gridDim.z > 1) {
        A += (size_t)blockIdx.z * sA;
        W += (size_t)blockIdx.z * sW;
        C += (size_t)blockIdx.z * sC;
        if (bias)  bias  += (size_t)blockIdx.z * sB;
        if (resid) resid += (size_t)blockIdx.z * sC;
    }
    __shared__ float As[2][ASMEM];
    __shared__ float Bs[2][BSMEM];
    int tid = threadIdx.x;
    int bm = blockIdx.y * 128;
    int bn = blockIdx.x * 64;
    int wid = tid >> 5, lane = tid & 31;
    int wm = wid >> 1, wn = wid & 1;
    int gid = lane >> 2, tig = lane & 3;

    // ldmatrix per-lane row/col selectors
    int rowA_sub = (lane & 7) + ((lane >> 3) & 1) * 8;
    int kselA = (lane >> 4) * 4;
    int rowB_sub = (lane & 7) + ((lane >> 4) & 1) * 8;
    int kselB = ((lane >> 3) & 1) * 4;

    uint32_t smemA = (uint32_t)__cvta_generic_to_shared(&As[0][0]);
    uint32_t smemB = (uint32_t)__cvta_generic_to_shared(&Bs[0][0]);

    // loaders
    int arr = tid >> 1, akc = (tid & 1) * 8;
    bool aact = (bm + arr) < M;
    const float* Ap = A + (size_t)(bm + arr) * K + akc;
    int brr = (tid >> 1) & 63, bkc = (tid & 1) * 8;
    bool bldr = tid < 128;
    bool wact = bldr && (bn + brr) < N;
    const float* Wp = W + (size_t)(bn + brr) * K + bkc;

    float acc[2][4][4];
    #pragma unroll
    for (int i = 0; i < 2; i++)
        #pragma unroll
        for (int j = 0; j < 4; j++)
            #pragma unroll
            for (int q = 0; q < 4; q++) acc[i][j][q] = 0.f;

    float4 ra0 = make_float4(0,0,0,0), ra1 = make_float4(0,0,0,0);
    float4 rb0 = make_float4(0,0,0,0), rb1 = make_float4(0,0,0,0);

    if (aact) { ra0 = *(const float4*)(Ap); ra1 = *(const float4*)(Ap + 4); }
    if (wact) { rb0 = *(const float4*)(Wp); rb1 = *(const float4*)(Wp + 4); }
    *(float4*)&As[0][arr * ASTRIDE + akc]     = ra0;
    *(float4*)&As[0][arr * ASTRIDE + akc + 4] = ra1;
    if (bldr) {
        *(float4*)&Bs[0][brr * ASTRIDE + bkc]     = rb0;
        *(float4*)&Bs[0][brr * ASTRIDE + bkc + 4] = rb1;
    }
    __syncthreads();

    int NT = K >> 4;
    for (int t = 0; t < NT; t++) {
        int buf = t & 1;
        if (t + 1 < NT) {
            int k0 = (t + 1) << 4;
            ra0 = make_float4(0,0,0,0); ra1 = make_float4(0,0,0,0);
            rb0 = make_float4(0,0,0,0); rb1 = make_float4(0,0,0,0);
            if (aact) { ra0 = *(const float4*)(Ap + k0); ra1 = *(const float4*)(Ap + k0 + 4); }
            if (wact) { rb0 = *(const float4*)(Wp + k0); rb1 = *(const float4*)(Wp + k0 + 4); }
        }
        uint32_t abase = smemA + buf * (ASMEM * 4);
        uint32_t bbase = smemB + buf * (BSMEM * 4);
        #pragma unroll
        for (int kh = 0; kh < 2; kh++) {
            uint32_t araw[2][4], braw[2][4];
            #pragma unroll
            for (int mt = 0; mt < 2; mt++) {
                int m0 = wm * 32 + mt * 16;
                uint32_t ad = abase + (uint32_t)(((m0 + rowA_sub) * ASTRIDE + kh * 8 + kselA) * 4);
                ldsm4(araw[mt], ad);
            }
            #pragma unroll
            for (int np = 0; np < 2; np++) {
                int n0 = wn * 32 + np * 16;
                uint32_t bd = bbase + (uint32_t)(((n0 + rowB_sub) * ASTRIDE + kh * 8 + kselB) * 4);
                ldsm4(braw[np], bd);
            }
            uint32_t ahi[2][4], alo[2][4], bhi[2][4], blo[2][4];
            #pragma unroll
            for (int mt = 0; mt < 2; mt++)
                #pragma unroll
                for (int q = 0; q < 4; q++) {
                    float v = __uint_as_float(araw[mt][q]);
                    uint32_t h = f2tf32(v);
                    ahi[mt][q] = h;
                    alo[mt][q] = f2tf32(v - __uint_as_float(h));
                }
            #pragma unroll
            for (int np = 0; np < 2; np++)
                #pragma unroll
                for (int q = 0; q < 4; q++) {
                    float v = __uint_as_float(braw[np][q]);
                    uint32_t h = f2tf32(v);
                    bhi[np][q] = h;
                    blo[np][q] = f2tf32(v - __uint_as_float(h));
                }
            #pragma unroll
            for (int mt = 0; mt < 2; mt++)
                #pragma unroll
                for (int nt = 0; nt < 4; nt++) {
                    int np = nt >> 1, off = (nt & 1) * 2;
                    float* d = acc[mt][nt];
                    mma_tf32(d, ahi[mt], bhi[np][off], bhi[np][off + 1]);
                    mma_tf32(d, alo[mt], bhi[np][off], bhi[np][off + 1]);
                    mma_tf32(d, ahi[mt], blo[np][off], blo[np][off + 1]);
                }
        }
        if (t + 1 < NT) {
            int nb = buf ^ 1;
            *(float4*)&As[nb][arr * ASTRIDE + akc]     = ra0;
            *(float4*)&As[nb][arr * ASTRIDE + akc + 4] = ra1;
            if (bldr) {
                *(float4*)&Bs[nb][brr * ASTRIDE + bkc]     = rb0;
                *(float4*)&Bs[nb][brr * ASTRIDE + bkc + 4] = rb1;
            }
            __syncthreads();
        }
    }

    // epilogue: c{0,1} -> (row gid, cols 2tig,2tig+1); c{2,3} -> row gid+8
    #pragma unroll
    for (int mt = 0; mt < 2; mt++) {
        #pragma unroll
        for (int half = 0; half < 2; half++) {
            int m = bm + wm * 32 + mt * 16 + gid + half * 8;
            if (m >= M) continue;
            #pragma unroll
            for (int nt = 0; nt < 4; nt++) {
                int n = bn + wn * 32 + nt * 8 + tig * 2;
                if (n >= N) continue;
                float v0 = acc[mt][nt][half * 2 + 0];
                float v1 = acc[mt][nt][half * 2 + 1];
                if (EPI == 0) {
                    if (bias) { v0 += bias[n]; v1 += bias[n + 1]; }
                } else if (EPI == 1) {
                    v0 = fmaxf(v0 + bias[n], 0.f);
                    v1 = fmaxf(v1 + bias[n + 1], 0.f);
                } else if (EPI == 2) {
                    if (bias) { v0 += bias[n]; v1 += bias[n + 1]; }
                    float2 r2 = *(const float2*)(resid + (size_t)m * N + n);
                    v0 += r2.x; v1 += r2.y;
                } else if (EPI == 3) {
                    if (n < DMOD) {
                        v0 += bias[n];
                        v1 += bias[n + 1];
                        v0 = (v0 > 20.f) ? v0 : log1pf(__expf(v0));
                        v1 = (v1 > 20.f) ? v1 : log1pf(__expf(v1));
                    }
                }
                float2 o; o.x = v0; o.y = v1;
                *(float2*)(C + (size_t)m * N + n) = o;
            }
        }
    }
}

// ---------------- depthwise causal conv (DCONV=2) + silu ----------------
__global__ void conv_silu(const float* __restrict__ xz, const float* __restrict__ cw,
                          const float* __restrict__ cb, float* __restrict__ xc, int l)
{
    int idx = blockIdx.x * 256 + threadIdx.x;
    if (idx >= 2 * MTOT * DMOD) return;
    int dir = idx / (MTOT * DMOD);
    int rem = idx - dir * (MTOT * DMOD);
    int row = rem >> 7;
    int d = rem & (DMOD - 1);
    int b = row / LTOK;
    int tau = row - b * LTOK;
    int t = dir ? (LTOK - 1 - tau) : tau;
    int ld = l * 2 + dir;
    float c0 = cw[(ld * DMOD + d) * 2 + 0];
    float c1 = cw[(ld * DMOD + d) * 2 + 1];
    float x1 = xz[((size_t)(b * LTOK + t)) * 512 + dir * 256 + d];
    float acc = x1 * c1 + cb[ld * DMOD + d];
    if (tau > 0) {
        int tp = dir ? (t + 1) : (t - 1);
        acc += xz[((size_t)(b * LTOK + tp)) * 512 + dir * 256 + d] * c0;
    }
    acc = acc / (1.f + __expf(-acc));
    xc[(size_t)dir * MTOT * DMOD + rem] = acc;
}

// ---------------- chunked selective scan (thread = d, 16 states in regs) ---------
__global__ __launch_bounds__(128) void scan_p1(
    const float* __restrict__ dbc, const float* __restrict__ xc,
    const float* __restrict__ A_log, float* __restrict__ sA, float* __restrict__ sH, int l)
{
    int d  = threadIdx.x;
    int c  = blockIdx.x;
    int b  = blockIdx.y;
    int dir = blockIdx.z;
    int ld = l * 2 + dir;

    float a[DST];
    {
        const float* Ab = A_log + ((size_t)(ld * DMOD + d)) * DST;
        #pragma unroll
        for (int q = 0; q < 4; q++) {
            float4 v = *(const float4*)(Ab + q * 4);
            a[q*4+0] = -__expf(v.x); a[q*4+1] = -__expf(v.y);
            a[q*4+2] = -__expf(v.z); a[q*4+3] = -__expf(v.w);
        }
    }
    const float* dbcp = dbc + (size_t)dir * MTOT * 160 + (size_t)b * LTOK * 160;
    const float* xcp  = xc  + (size_t)dir * MTOT * DMOD + (size_t)b * LTOK * DMOD;

    int t0 = c * CLEN;
    int t1 = t0 + CLEN; if (t1 > LTOK) t1 = LTOK;

    float Aacc[DST], h[DST];
    #pragma unroll
    for (int n = 0; n < DST; n++) { Aacc[n] = 1.f; h[n] = 0.f; }

    for (int t = t0; t < t1; t++) {
        const float* row = dbcp + (size_t)t * 160;
        float delta = row[d];
        float xcv   = xcp[(size_t)t * DMOD + d];
        float dbx   = delta * xcv;
        float Bv[DST];
        #pragma unroll
        for (int q = 0; q < 4; q++) {
            float4 v = *(const float4*)(row + 128 + q * 4);
            Bv[q*4+0] = v.x; Bv[q*4+1] = v.y; Bv[q*4+2] = v.z; Bv[q*4+3] = v.w;
        }
        #pragma unroll
        for (int n = 0; n < DST; n++) {
            float dA = __expf(delta * a[n]);
            Aacc[n] *= dA;
            h[n] = fmaf(dA, h[n], dbx * Bv[n]);
        }
    }
    size_t base = (((size_t)(b * 2 + dir) * NCH + c) * DMOD + d) * DST;
    #pragma unroll
    for (int q = 0; q < 4; q++) {
        *(float4*)(sA + base + q * 4) = make_float4(Aacc[q*4], Aacc[q*4+1], Aacc[q*4+2], Aacc[q*4+3]);
        *(float4*)(sH + base + q * 4) = make_float4(h[q*4], h[q*4+1], h[q*4+2], h[q*4+3]);
    }
}

__global__ void scan_comb(const float* __restrict__ sA, const float* __restrict__ sH,
                          float* __restrict__ sS)
{
    int idx = blockIdx.x * 256 + threadIdx.x;
    if (idx >= BQ * 2 * DMOD * DST) return;
    int dn = idx & (DMOD * DST - 1);
    int bd = idx >> 11;
    size_t base = (size_t)bd * NCH * DMOD * DST + dn;
    float h = 0.f;
    #pragma unroll
    for (int c = 0; c < NCH; c++) {
        size_t p = base + (size_t)c * DMOD * DST;
        sS[p] = h;
        h = fmaf(sA[p], h, sH[p]);
    }
}

__global__ __launch_bounds__(128) void scan_p2(
    const float* __restrict__ dbc, const float* __restrict__ xc,
    const float* __restrict__ xz, const float* __restrict__ A_log,
    const float* __restrict__ Dpar, const float* __restrict__ sS,
    float* __restrict__ y, int l)
{
    int d  = threadIdx.x;
    int c  = blockIdx.x;
    int b  = blockIdx.y;
    int dir = blockIdx.z;
    int ld = l * 2 + dir;

    float a[DST];
    {
        const float* Ab = A_log + ((size_t)(ld * DMOD + d)) * DST;
        #pragma unroll
        for (int q = 0; q < 4; q++) {
            float4 v = *(const float4*)(Ab + q * 4);
            a[q*4+0] = -__expf(v.x); a[q*4+1] = -__expf(v.y);
            a[q*4+2] = -__expf(v.z); a[q*4+3] = -__expf(v.w);
        }
    }
    float Dp = Dpar[ld * DMOD + d];
    const float* dbcp = dbc + (size_t)dir * MTOT * 160 + (size_t)b * LTOK * 160;
    const float* xcp  = xc  + (size_t)dir * MTOT * DMOD + (size_t)b * LTOK * DMOD;
    const float* zp   = xz  + (size_t)b * LTOK * 512 + 128 + dir * 256;
    float*       yp   = y   + (size_t)b * LTOK * 256 + dir * 128;

    int t0 = c * CLEN;
    int t1 = t0 + CLEN; if (t1 > LTOK) t1 = LTOK;

    float h[DST];
    {
        size_t base = (((size_t)(b * 2 + dir) * NCH + c) * DMOD + d) * DST;
        #pragma unroll
        for (int q = 0; q < 4; q++) {
            float4 v = *(const float4*)(sS + base + q * 4);
            h[q*4+0] = v.x; h[q*4+1] = v.y; h[q*4+2] = v.z; h[q*4+3] = v.w;
        }
    }

    for (int tau = t0; tau < t1; tau++) {
        const float* row = dbcp + (size_t)tau * 160;
        float delta = row[d];
        float xcv   = xcp[(size_t)tau * DMOD + d];
        float dbx   = delta * xcv;
        float Bv[DST], Cv[DST];
        #pragma unroll
        for (int q = 0; q < 4; q++) {
            float4 v = *(const float4*)(row + 128 + q * 4);
            Bv[q*4+0] = v.x; Bv[q*4+1] = v.y; Bv[q*4+2] = v.z; Bv[q*4+3] = v.w;
            float4 u = *(const float4*)(row + 144 + q * 4);
            Cv[q*4+0] = u.x; Cv[q*4+1] = u.y; Cv[q*4+2] = u.z; Cv[q*4+3] = u.w;
        }
        float acc = 0.f;
        #pragma unroll
        for (int n = 0; n < DST; n++) {
            float dA = __expf(delta * a[n]);
            h[n] = fmaf(dA, h[n], dbx * Bv[n]);
            acc = fmaf(h[n], Cv[n], acc);
        }
        int t = dir ? (LTOK - 1 - tau) : tau;
        float zv = zp[(size_t)t * 512 + d];
        float sz = zv / (1.f + __expf(-zv));
        yp[(size_t)t * 256 + d] = (acc + Dp * xcv) * sz;
    }
}

// ---------------- layernorm: warp per row, 8 rows/block ----------------
__global__ __launch_bounds__(256) void ln_k(const float* __restrict__ in, float* __restrict__ out,
                                            const float* __restrict__ w, const float* __restrict__ b)
{
    int warp = threadIdx.x >> 5, lane = threadIdx.x & 31;
    int row = blockIdx.x * 8 + warp;
    const float4 v4 = *(const float4*)(in + (size_t)row * DMOD + lane * 4);
    float s = v4.x + v4.y + v4.z + v4.w;
    #pragma unroll
    for (int o = 16; o; o >>= 1) s += __shfl_xor_sync(0xffffffffu, s, o);
    float mu = s * (1.f / 128.f);
    float dx = v4.x - mu, dy = v4.y - mu, dz = v4.z - mu, dw = v4.w - mu;
    float q = dx*dx + dy*dy + dz*dz + dw*dw;
    #pragma unroll
    for (int o = 16; o; o >>= 1) q += __shfl_xor_sync(0xffffffffu, q, o);
    float rs = rsqrtf(q * (1.f / 128.f) + 1e-5f);
    float4 w4 = *(const float4*)(w + lane * 4);
    float4 b4 = *(const float4*)(b + lane * 4);
    float4 o4;
    o4.x = dx * rs * w4.x + b4.x;
    o4.y = dy * rs * w4.y + b4.y;
    o4.z = dz * rs * w4.z + b4.z;
    o4.w = dw * rs * w4.w + b4.w;
    *(float4*)(out + (size_t)row * DMOD + lane * 4) = o4;
}

// ---------------- final transposed write ----------------
__global__ void write_out(const float* __restrict__ P, float* __restrict__ out)
{
    int idx = blockIdx.x * 256 + threadIdx.x;
    if (idx >= BQ * PREDN * NVAR) return;
    int v = idx & (NVAR - 1);
    int p = (idx >> 10) % PREDN;
    int b = idx / (PREDN * NVAR);
    out[idx] = P[((size_t)(b * LTOK + v)) * PREDN + p];
}

// ---------------- launcher ----------------
extern "C" void kernel_launch(void* const* d_in, const int* in_sizes, int n_in,
                              void* d_out, int out_size)
{
    const float* x_enc     = (const float*)d_in[0];
    const float* x_mark    = (const float*)d_in[1];
    const float* emb_w     = (const float*)d_in[4];
    const float* emb_b     = (const float*)d_in[5];
    const float* in_proj_w = (const float*)d_in[6];
    const float* conv_w    = (const float*)d_in[7];
    const float* conv_b    = (const float*)d_in[8];
    const float* x_proj_w  = (const float*)d_in[9];
    const float* dt_proj_w = (const float*)d_in[10];
    const float* dt_proj_b = (const float*)d_in[11];
    const float* A_log     = (const float*)d_in[12];
    const float* D_param   = (const float*)d_in[13];
    const float* out_projw = (const float*)d_in[14];
    const float* norm1_w   = (const float*)d_in[15];
    const float* norm1_b   = (const float*)d_in[16];
    const float* norm2_w   = (const float*)d_in[17];
    const float* norm2_b   = (const float*)d_in[18];
    const float* ffn_w1    = (const float*)d_in[19];
    const float* ffn_b1    = (const float*)d_in[20];
    const float* ffn_w2    = (const float*)d_in[21];
    const float* ffn_b2    = (const float*)d_in[22];
    const float* fnorm_w   = (const float*)d_in[23];
    const float* fnorm_b   = (const float*)d_in[24];
    const float* proj_w    = (const float*)d_in[25];
    const float* proj_b    = (const float*)d_in[26];

    float *ptok, *ph, *pln1, *pffn, *pxz, *pxc, *pdbc, *py, *ppo, *pwxp, *pwop;
    float *psA, *psH, *psS;
    cudaGetSymbolAddress((void**)&ptok, g_tok);
    cudaGetSymbolAddress((void**)&ph,   g_h);
    cudaGetSymbolAddress((void**)&pln1, g_ln1);
    cudaGetSymbolAddress((void**)&pffn, g_ffn);
    cudaGetSymbolAddress((void**)&pxz,  g_xz);
    cudaGetSymbolAddress((void**)&pxc,  g_xc);
    cudaGetSymbolAddress((void**)&pdbc, g_dbc);
    cudaGetSymbolAddress((void**)&py,   g_y);
    cudaGetSymbolAddress((void**)&ppo,  g_po);
    cudaGetSymbolAddress((void**)&pwxp, g_wxp);
    cudaGetSymbolAddress((void**)&pwop, g_wop);
    cudaGetSymbolAddress((void**)&psA,  g_sA);
    cudaGetSymbolAddress((void**)&psH,  g_sH);
    cudaGetSymbolAddress((void**)&psS,  g_sS);

    const int MT = (MTOT + 127) / 128;   // 65

    // launch index 3 = in_proj GEMM of layer 0 (the one ncu captures)
    tok_prep<<<dim3(SEQ / 32, NVAR / 32, BQ), dim3(32, 8)>>>(x_enc, ptok);          // 0
    mark_prep<<<(BQ * TFEAT * SEQ + 255) / 256, 256>>>(x_mark, ptok);               // 1
    gemm_tc<0><<<dim3(2, MT), 256>>>(ptok, emb_w, emb_b, nullptr, ph,               // 2
                                     MTOT, DMOD, SEQ, 0, 0, 0, 0);
    gemm_tc<0><<<dim3(8, MT), 256>>>(ph, in_proj_w, nullptr, nullptr, pxz,          // 3 (profiled)
                                     MTOT, 512, DMOD, 0, 0, 0, 0);
    prep_wd<<<dim3(80, 4), 256>>>(x_proj_w, dt_proj_w, pwxp);
    prep_wop<<<(2 * DMOD * 256 + 255) / 256, 256>>>(out_projw, pwop);

    for (int l = 0; l < 2; l++) {
        if (l > 0)
            gemm_tc<0><<<dim3(8, MT), 256>>>(ph, in_proj_w + (size_t)l * 2 * 256 * DMOD,
                                             nullptr, nullptr, pxz, MTOT, 512, DMOD, 0, 0, 0, 0);
        conv_silu<<<(2 * MTOT * DMOD + 255) / 256, 256>>>(pxz, conv_w, conv_b, pxc, l);
        gemm_tc<3><<<dim3(3, MT, 2), 256>>>(pxc, pwxp + (size_t)l * 2 * 160 * DMOD,
                                            dt_proj_b + (size_t)l * 2 * DMOD, nullptr, pdbc,
                                            MTOT, 160, DMOD,
                                            (size_t)MTOT * DMOD, (size_t)160 * DMOD,
                                            (size_t)DMOD, (size_t)MTOT * 160);
        scan_p1<<<dim3(NCH, BQ, 2), 128>>>(pdbc, pxc, A_log, psA, psH, l);
        scan_comb<<<(BQ * 2 * DMOD * DST + 255) / 256, 256>>>(psA, psH, psS);
        scan_p2<<<dim3(NCH, BQ, 2), 128>>>(pdbc, pxc, pxz, A_log, D_param, psS, py, l);
        gemm_tc<2><<<dim3(2, MT), 256>>>(py, pwop + (size_t)l * DMOD * 256,
                                         nullptr, ph, ph, MTOT, DMOD, 256, 0, 0, 0, 0);
        ln_k<<<MTOT / 8, 256>>>(ph, pln1, norm1_w + l * DMOD, norm1_b + l * DMOD);
        gemm_tc<1><<<dim3(2, MT), 256>>>(pln1, ffn_w1 + (size_t)l * DMOD * DMOD,
                                         ffn_b1 + l * DMOD, nullptr, pffn,
                                         MTOT, DMOD, DMOD, 0, 0, 0, 0);
        gemm_tc<2><<<dim3(2, MT), 256>>>(pffn, ffn_w2 + (size_t)l * DMOD * DMOD,
                                         ffn_b2 + l * DMOD, pln1, ph, MTOT, DMOD, DMOD, 0, 0, 0, 0);
        ln_k<<<MTOT / 8, 256>>>(ph, ph, norm2_w + l * DMOD, norm2_b + l * DMOD);
    }

    ln_k<<<MTOT / 8, 256>>>(ph, pln1, fnorm_w, fnorm_b);
    gemm_tc<0><<<dim3(2, MT), 256>>>(pln1, proj_w, proj_b, nullptr, ppo,
                                     MTOT, PREDN, DMOD, 0, 0, 0, 0);
    write_out<<<(BQ * PREDN * NVAR + 255) / 256, 256>>>(ppo, (float*)d_out);
}